// round 13
// baseline (speedup 1.0000x reference)
#include <cuda_runtime.h>
#include <math.h>

// Problem constants (fixed shapes: x is (8,1,64,64) float32)
#define B_DIM 8
#define H_DIM 64
#define W_DIM 64
#define N_PIX (H_DIM * W_DIM)          // 4096
#define M0_CONST 0.01f

#define NOFF (127 * 127)               // 16129 offsets, sorted by d2
#define MAXD2 (63 * 63 * 2)
#define HOT 256                        // entries processed by the hot loop
#define NCH (HOT / 16)                 // 16 chunks
#define HOTX (HOT + 16)                // +1 chunk of prefetch slack
#define HY 10                          // halo rows (top & bottom)
#define HX 12                          // halo cols left (right halo = 12)
#define PSTR 88                        // padded row stride (12+64+12)
#define PROWS 84                       // 10+64+10
#define PSZ (PROWS * PSTR)             // 7392 floats

struct OffTable { unsigned int v[NOFF]; };

constexpr OffTable make_table() {
    OffTable t{};
    int bins[MAXD2 + 1] = {};
    for (int dy = -63; dy <= 63; ++dy)
        for (int dx = -63; dx <= 63; ++dx)
            bins[dy * dy + dx * dx]++;
    int acc = 0;
    for (int d = 0; d <= MAXD2; ++d) { int c = bins[d]; bins[d] = acc; acc += c; }
    for (int dy = -63; dy <= 63; ++dy)
        for (int dx = -63; dx <= 63; ++dx) {
            int d2 = dy * dy + dx * dx;
            t.v[bins[d2]++] = ((unsigned)d2 << 16)
                            | ((unsigned)(dy + 63) << 8)
                            | (unsigned)(dx + 63);
        }
    return t;
}

__device__ constexpr OffTable g_off = make_table();   // fallback path only

// Hot prefix as compile-time constants: padded-smem offset + float d2.
struct Hot { int c[HOTX]; float d2[HOTX]; };
constexpr Hot make_hot() {
    Hot h{};
    OffTable t = make_table();
    for (int k = 0; k < HOTX; ++k) {
        int dy = (int)((t.v[k] >> 8) & 255u) - 63;
        int dx = (int)(t.v[k] & 255u) - 63;
        h.c[k]  = (dy + HY) * PSTR + (dx + HX);
        h.d2[k] = (float)(t.v[k] >> 16);
    }
    return h;
}
__device__ constexpr Hot g_hot = make_hot();

// Halo must cover every hot (and prefetch-slack) entry.
constexpr bool halo_ok() {
    OffTable t = make_table();
    for (int k = 0; k < HOTX; ++k) {
        int dy = (int)((t.v[k] >> 8) & 255u) - 63;
        int dx = (int)(t.v[k] & 255u) - 63;
        if (dy < -HY || dy > HY || dx < -HX || dx > HX) return false;
    }
    return true;
}
static_assert(halo_ok(), "halo too small for HOTX prefix");

// Gather one 16-entry chunk; all addresses are [base + compile-time imm].
__device__ __forceinline__ void loadW(const float* __restrict__ pimg, int bi,
                                      int ch, float* w) {
    #pragma unroll
    for (int j = 0; j < 16; ++j)
        w[j] = pimg[bi + g_hot.c[ch * 16 + j]];
}

// Exact clipped evaluation of one chunk (crossing chunks only).
__device__ __forceinline__ float clip16(const float* w, int ch, float r) {
    float s0 = 0.f, s1 = 0.f, s2 = 0.f, s3 = 0.f;
    #pragma unroll
    for (int g = 0; g < 4; ++g) {
        const int k = ch * 16 + g * 4;
        const float w0 = w[g * 4], w1 = w[g * 4 + 1];
        const float w2 = w[g * 4 + 2], w3 = w[g * 4 + 3];
        const float p1 = w0;
        const float p2 = p1 + w1;
        const float p3 = p2 + w2;
        s0 = fmaf(fmaxf(0.f, fminf(w0, r)),      g_hot.d2[k],     s0);
        s1 = fmaf(fmaxf(0.f, fminf(w1, r - p1)), g_hot.d2[k + 1], s1);
        s2 = fmaf(fmaxf(0.f, fminf(w2, r - p2)), g_hot.d2[k + 2], s2);
        s3 = fmaf(fmaxf(0.f, fminf(w3, r - p3)), g_hot.d2[k + 3], s3);
        r -= (p3 + w3);
    }
    return (s0 + s1) + (s2 + s3);
}

// Cheap pass: unclipped chunk mass + d2-weighted sum; clip fixup only when
// a lane's remaining mass crosses inside this chunk (warp-voted, ~once/lane).
__device__ __forceinline__ void procChunk(const float* w, int ch,
                                          float& r, float& s) {
    float wsa = w[0] + w[4],  wsb = w[1] + w[5];
    float wsc = w[2] + w[6],  wsd = w[3] + w[7];
    wsa += w[8];  wsb += w[9];  wsc += w[10]; wsd += w[11];
    wsa += w[12]; wsb += w[13]; wsc += w[14]; wsd += w[15];
    const float ws = (wsa + wsb) + (wsc + wsd);

    float sa = w[0] * g_hot.d2[ch * 16];
    float sb = w[1] * g_hot.d2[ch * 16 + 1];
    float sc = w[2] * g_hot.d2[ch * 16 + 2];
    float sd_ = w[3] * g_hot.d2[ch * 16 + 3];
    #pragma unroll
    for (int j = 4; j < 16; j += 4) {
        sa  = fmaf(w[j],     g_hot.d2[ch * 16 + j],     sa);
        sb  = fmaf(w[j + 1], g_hot.d2[ch * 16 + j + 1], sb);
        sc  = fmaf(w[j + 2], g_hot.d2[ch * 16 + j + 2], sc);
        sd_ = fmaf(w[j + 3], g_hot.d2[ch * 16 + j + 3], sd_);
    }
    const float sd = (sa + sb) + (sc + sd_);

    const bool fix = (r > 0.f) & (r < ws);
    float contrib;
    if (__any_sync(0xFFFFFFFFu, fix)) {
        const float cs = clip16(w, ch, r);
        contrib = fix ? cs : ((r >= ws) ? sd : 0.f);
    } else {
        contrib = (r >= ws) ? sd : 0.f;
    }
    s += contrib;
    r -= ws;
}

// One block = 4 strided rows (slab, slab+16, slab+32, slab+48) of one image:
// striding balances edge-row cost across CTAs (1 CTA/SM -> slowest CTA sets
// kernel time). Image lives zero-padded in smem; hot loop is LDS [R+imm].
__global__ __launch_bounds__(256) void dtm_kernel(const float* __restrict__ xin,
                                                  float* __restrict__ out) {
    __shared__ __align__(16) float pimg[PSZ];
    __shared__ float swarp[8];

    const int tid   = threadIdx.x;
    const int lane  = tid & 31;
    const int wid   = tid >> 5;
    const int batch = blockIdx.x >> 4;
    const int slab  = blockIdx.x & 15;
    const float* img = xin + batch * N_PIX;

    // Issue the 4 image loads first (long latency), then zero the pad.
    const float4 v0 = ((const float4*)img)[tid];
    const float4 v1 = ((const float4*)img)[tid + 256];
    const float4 v2 = ((const float4*)img)[tid + 512];
    const float4 v3 = ((const float4*)img)[tid + 768];

    const float4 z4 = make_float4(0.f, 0.f, 0.f, 0.f);
    #pragma unroll
    for (int j = 0; j < 8; ++j) {
        const int idx = tid + j * 256;
        if (idx < PSZ / 4) ((float4*)pimg)[idx] = z4;
    }
    __syncthreads();                              // pad zeroed

    // Scatter image into padded layout (16B-aligned stores) + mass partial.
    const int y0 = tid >> 4;
    const int x0 = (tid & 15) << 2;
    *(float4*)&pimg[(y0 + HY)      * PSTR + x0 + HX] = v0;
    *(float4*)&pimg[(y0 + HY + 16) * PSTR + x0 + HX] = v1;
    *(float4*)&pimg[(y0 + HY + 32) * PSTR + x0 + HX] = v2;
    *(float4*)&pimg[(y0 + HY + 48) * PSTR + x0 + HX] = v3;

    float part = ((v0.x + v0.y) + (v0.z + v0.w)) + ((v1.x + v1.y) + (v1.z + v1.w))
               + ((v2.x + v2.y) + (v2.z + v2.w)) + ((v3.x + v3.y) + (v3.z + v3.w));
    #pragma unroll
    for (int o = 16; o > 0; o >>= 1)
        part += __shfl_xor_sync(0xFFFFFFFFu, part, o);
    if (lane == 0) swarp[wid] = part;
    __syncthreads();                              // image + partials published

    float total;
    {
        float4 a = ((const float4*)swarp)[0];
        float4 b = ((const float4*)swarp)[1];
        total = ((a.x + a.y) + (a.z + a.w)) + ((b.x + b.y) + (b.z + b.w));
    }
    const float m = M0_CONST * total;

    const int x = tid & 63;
    const int y = slab + ((tid >> 6) << 4);       // strided row assignment
    const int bi = y * PSTR + x;

    float r = m;                                  // remaining mass
    float s = 0.f;

    if (m > 0.0f) {
        float wA[16], wB[16];
        bool done = false;
        loadW(pimg, bi, 0, wA);
        // 2-stage pipeline: chunk k+1's gathers issue before chunk k's FP.
        #pragma unroll
        for (int cp = 0; cp < NCH / 2; ++cp) {
            loadW(pimg, bi, 2 * cp + 1, wB);
            procChunk(wA, 2 * cp, r, s);
            if (__all_sync(0xFFFFFFFFu, r <= 0.f)) { done = true; break; }
            loadW(pimg, bi, 2 * cp + 2, wA);      // last iter: slack chunk
            procChunk(wB, 2 * cp + 1, r, s);
            if (__all_sync(0xFFFFFFFFu, r <= 0.f)) { done = true; break; }
        }

        // Fallback past the hot prefix (pathological inputs only).
        if (!done && __any_sync(0xFFFFFFFFu, r > 0.f)) {
            for (int k = HOT; k < NOFF; ++k) {
                const unsigned p = g_off.v[k];
                const int ny = y + (int)((p >> 8) & 255u) - 63;
                const int nx = x + (int)(p & 255u) - 63;
                if ((unsigned)ny < (unsigned)H_DIM &&
                    (unsigned)nx < (unsigned)W_DIM) {
                    const float w   = img[(ny << 6) | nx];
                    const float eff = fmaxf(0.f, fminf(w, r));
                    s = fmaf(eff, (float)(p >> 16), s);
                    r -= w;
                }
                if (__all_sync(0xFFFFFFFFu, r <= 0.f)) break;
            }
        }
    }

    const float result = (total > 0.0f) ? sqrtf(s / m) : 0.0f;
    out[batch * N_PIX + (y << 6) + x] = result;
}

extern "C" void kernel_launch(void* const* d_in, const int* in_sizes, int n_in,
                              void* d_out, int out_size) {
    const float* xin = (const float*)d_in[0];
    float* out = (float*)d_out;
    (void)in_sizes; (void)n_in; (void)out_size;
    dtm_kernel<<<B_DIM * (N_PIX / 256), 256>>>(xin, out);
}